// round 2
// baseline (speedup 1.0000x reference)
#include <cuda_runtime.h>
#include <cuda_bf16.h>
#include <mma.h>
#include <cstdint>

using namespace nvcuda;

#define Bn 32
#define En 512
#define Nn 4096
#define IMG 224

// ----------------------------- device scratch -----------------------------
__device__ __nv_bfloat16 g_xbf[(size_t)Bn * En * Nn];   // 134 MB bf16 copy of x
__device__ float g_mean[Bn * En];                        // row means (temporal grid)
__device__ float g_inv[Bn * En];                         // 1/(||x - mean|| + 1e-8)
__device__ float g_spatial[Bn * Nn];                     // column means
__device__ float g_corr[(size_t)Bn * En * En];           // raw Gram G = x x^T (fp32)
__device__ unsigned g_mm[6];                             // encoded {min,max} per view

// ----------------------------- helpers -----------------------------
__device__ __forceinline__ unsigned fenc(float f) {
    unsigned u = __float_as_uint(f);
    return (u & 0x80000000u) ? ~u : (u | 0x80000000u);
}
__device__ __forceinline__ float fdec(unsigned e) {
    return (e & 0x80000000u) ? __uint_as_float(e ^ 0x80000000u)
                             : __uint_as_float(~e);
}

// ----------------------------- kernel 0: init -----------------------------
__global__ void k_init() {
    int t = threadIdx.x;
    if (t < 6) g_mm[t] = (t & 1) ? 0u : 0xFFFFFFFFu;  // even=min slot, odd=max slot
}

// ------------------- kernel 1: row stats + bf16 convert -------------------
// One block per row (b*512+e). Computes mean, 1/(||xc||+eps), bf16 copy.
__global__ void __launch_bounds__(256) k_rowstats(const float* __restrict__ x) {
    const int row = blockIdx.x;
    const float4* src = reinterpret_cast<const float4*>(x) + (size_t)row * (Nn / 4);
    uint2* dst = reinterpret_cast<uint2*>(g_xbf) + (size_t)row * (Nn / 4);
    float s = 0.f, ss = 0.f;
#pragma unroll
    for (int k = 0; k < 4; k++) {
        int i = threadIdx.x + k * 256;
        float4 v = src[i];
        s += v.x + v.y + v.z + v.w;
        ss += v.x * v.x + v.y * v.y + v.z * v.z + v.w * v.w;
        unsigned ax = (unsigned)__bfloat16_as_ushort(__float2bfloat16_rn(v.x));
        unsigned ay = (unsigned)__bfloat16_as_ushort(__float2bfloat16_rn(v.y));
        unsigned az = (unsigned)__bfloat16_as_ushort(__float2bfloat16_rn(v.z));
        unsigned aw = (unsigned)__bfloat16_as_ushort(__float2bfloat16_rn(v.w));
        uint2 o;
        o.x = ax | (ay << 16);
        o.y = az | (aw << 16);
        dst[i] = o;
    }
#pragma unroll
    for (int o = 16; o; o >>= 1) {
        s += __shfl_down_sync(0xFFFFFFFFu, s, o);
        ss += __shfl_down_sync(0xFFFFFFFFu, ss, o);
    }
    __shared__ float sh[16];
    int w = threadIdx.x >> 5, l = threadIdx.x & 31;
    if (l == 0) { sh[w] = s; sh[w + 8] = ss; }
    __syncthreads();
    if (threadIdx.x == 0) {
        float S = 0.f, SS = 0.f;
#pragma unroll
        for (int i = 0; i < 8; i++) { S += sh[i]; SS += sh[i + 8]; }
        float m = S * (1.f / (float)Nn);
        g_mean[row] = m;
        float var = SS - S * m;  // sum (x-m)^2
        float r = sqrtf(fmaxf(var, 0.f));
        g_inv[row] = 1.f / (r + 1e-8f);
    }
}

// ------------------------ kernel 2: column means ------------------------
__global__ void __launch_bounds__(256) k_colmean(const float* __restrict__ x) {
    int b = blockIdx.y;
    int n = blockIdx.x * 256 + threadIdx.x;
    const float* p = x + (size_t)b * En * Nn + n;
    float s0 = 0.f, s1 = 0.f, s2 = 0.f, s3 = 0.f;
#pragma unroll 4
    for (int e = 0; e < En; e += 4) {
        s0 += p[(size_t)(e + 0) * Nn];
        s1 += p[(size_t)(e + 1) * Nn];
        s2 += p[(size_t)(e + 2) * Nn];
        s3 += p[(size_t)(e + 3) * Nn];
    }
    g_spatial[b * Nn + n] = (s0 + s1 + s2 + s3) * (1.f / (float)En);
}

// --------------------- kernel 3: batched Gram (wmma) ---------------------
// Per batch: G = x x^T, x [512,4096] bf16. 128x128 tiles, symmetric:
// compute tile-pairs (ti,tj) with tj>=ti, mirror-store the transpose.
__global__ void __launch_bounds__(256) k_gemm() {
    const int ti_tab[10] = {0, 0, 0, 0, 1, 1, 1, 2, 2, 3};
    const int tj_tab[10] = {0, 1, 2, 3, 1, 2, 3, 2, 3, 3};
    const int ti = ti_tab[blockIdx.x];
    const int tj = tj_tab[blockIdx.x];
    const int b = blockIdx.y;

    __shared__ __nv_bfloat16 sA[128 * 48];  // 32-col tiles padded to 48 (96B rows, 16B aligned)
    __shared__ __nv_bfloat16 sB[128 * 48];

    const __nv_bfloat16* X = g_xbf + (size_t)b * En * Nn;
    const int t = threadIdx.x;
    const int wid = t >> 5;
    const int wm = wid >> 2;   // 0..1  (64-row strip)
    const int wn = wid & 3;    // 0..3  (32-col strip)

    wmma::fragment<wmma::accumulator, 16, 16, 16, float> acc[4][2];
#pragma unroll
    for (int i = 0; i < 4; i++)
#pragma unroll
        for (int j = 0; j < 2; j++) wmma::fill_fragment(acc[i][j], 0.f);

    for (int kc = 0; kc < Nn / 32; kc++) {
        // load 128x32 bf16 tiles for A (rows ti*128..) and B (rows tj*128..)
#pragma unroll
        for (int i = 0; i < 2; i++) {
            int idx = t + 256 * i;            // 0..511
            int r = idx >> 2;                 // 0..127
            int seg = idx & 3;                // 0..3, 8 bf16 each
            const uint4* pa = reinterpret_cast<const uint4*>(
                X + (size_t)(ti * 128 + r) * Nn + kc * 32) + seg;
            const uint4* pb = reinterpret_cast<const uint4*>(
                X + (size_t)(tj * 128 + r) * Nn + kc * 32) + seg;
            *reinterpret_cast<uint4*>(&sA[r * 48 + seg * 8]) = *pa;
            *reinterpret_cast<uint4*>(&sB[r * 48 + seg * 8]) = *pb;
        }
        __syncthreads();
#pragma unroll
        for (int kk = 0; kk < 2; kk++) {
            wmma::fragment<wmma::matrix_a, 16, 16, 16, __nv_bfloat16, wmma::row_major> af[4];
            wmma::fragment<wmma::matrix_b, 16, 16, 16, __nv_bfloat16, wmma::col_major> bf[2];
#pragma unroll
            for (int i = 0; i < 4; i++)
                wmma::load_matrix_sync(af[i], &sA[(wm * 64 + i * 16) * 48 + kk * 16], 48);
#pragma unroll
            for (int j = 0; j < 2; j++)
                wmma::load_matrix_sync(bf[j], &sB[(wn * 32 + j * 16) * 48 + kk * 16], 48);
#pragma unroll
            for (int i = 0; i < 4; i++)
#pragma unroll
                for (int j = 0; j < 2; j++)
                    wmma::mma_sync(acc[i][j], af[i], bf[j], acc[i][j]);
        }
        __syncthreads();
    }

    float* C = g_corr + (size_t)b * En * En;
#pragma unroll
    for (int i = 0; i < 4; i++) {
#pragma unroll
        for (int j = 0; j < 2; j++) {
            int rm = ti * 128 + wm * 64 + i * 16;
            int cn = tj * 128 + wn * 32 + j * 16;
            wmma::store_matrix_sync(&C[(size_t)rm * En + cn], acc[i][j], En,
                                    wmma::mem_row_major);
            if (ti != tj)
                wmma::store_matrix_sync(&C[(size_t)cn * En + rm], acc[i][j], En,
                                        wmma::mem_col_major);  // transpose mirror
        }
    }
}

// ---------------- kernel 4: bilinear resize + global min/max ----------------
// grid.y = view (0 temporal 23x23, 1 spatial 64x64, 2 correlation 512x512)
// Correlation values are computed lazily from the raw Gram.
__global__ void __launch_bounds__(256) k_resize(float* __restrict__ out) {
    const int v = blockIdx.y;
    const int id = blockIdx.x * 256 + threadIdx.x;  // 0 .. 32*224*224-1
    const int b = id / (IMG * IMG);
    const int rem = id - b * (IMG * IMG);
    const int y = rem / IMG;
    const int xw = rem - y * IMG;

    const int size = (v == 0) ? 23 : (v == 1) ? 64 : 512;
    const float scale = (float)size / (float)IMG;

    float rr = fmaxf(((float)y + 0.5f) * scale - 0.5f, 0.f);
    int r0 = min((int)floorf(rr), size - 1);
    int r1 = min(r0 + 1, size - 1);
    float wr = rr - (float)r0;
    float cc = fmaxf(((float)xw + 0.5f) * scale - 0.5f, 0.f);
    int c0 = min((int)floorf(cc), size - 1);
    int c1 = min(c0 + 1, size - 1);
    float wc = cc - (float)c0;

    float v00, v01, v10, v11;
    if (v == 0) {
        const float* M = g_mean + b * En;
        int g00 = r0 * 23 + c0, g01 = r0 * 23 + c1, g10 = r1 * 23 + c0, g11 = r1 * 23 + c1;
        v00 = (g00 < En) ? M[g00] : 0.f;
        v01 = (g01 < En) ? M[g01] : 0.f;
        v10 = (g10 < En) ? M[g10] : 0.f;
        v11 = (g11 < En) ? M[g11] : 0.f;
    } else if (v == 1) {
        const float* S = g_spatial + b * Nn;
        v00 = S[r0 * 64 + c0]; v01 = S[r0 * 64 + c1];
        v10 = S[r1 * 64 + c0]; v11 = S[r1 * 64 + c1];
    } else {
        const float* C = g_corr + (size_t)b * En * En;
        const float* M = g_mean + b * En;
        const float* I = g_inv + b * En;
        float m0 = M[r0], m1 = M[r1], i0 = I[r0], i1 = I[r1];
        float mc0 = M[c0], mc1 = M[c1], ic0 = I[c0], ic1 = I[c1];
        v00 = (C[(size_t)r0 * En + c0] - (float)Nn * m0 * mc0) * i0 * ic0;
        v01 = (C[(size_t)r0 * En + c1] - (float)Nn * m0 * mc1) * i0 * ic1;
        v10 = (C[(size_t)r1 * En + c0] - (float)Nn * m1 * mc0) * i1 * ic0;
        v11 = (C[(size_t)r1 * En + c1] - (float)Nn * m1 * mc1) * i1 * ic1;
    }
    float top = v00 * (1.f - wc) + v01 * wc;
    float bot = v10 * (1.f - wc) + v11 * wc;
    float val = top * (1.f - wr) + bot * wr;

    out[((size_t)b * 3 + v) * (IMG * IMG) + rem] = val;

    // block min/max reduction -> one atomic pair per block
    float mn = val, mx = val;
#pragma unroll
    for (int o = 16; o; o >>= 1) {
        mn = fminf(mn, __shfl_down_sync(0xFFFFFFFFu, mn, o));
        mx = fmaxf(mx, __shfl_down_sync(0xFFFFFFFFu, mx, o));
    }
    __shared__ float smn[8], smx[8];
    int w = threadIdx.x >> 5, l = threadIdx.x & 31;
    if (l == 0) { smn[w] = mn; smx[w] = mx; }
    __syncthreads();
    if (threadIdx.x == 0) {
        float bmn = smn[0], bmx = smx[0];
#pragma unroll
        for (int i = 1; i < 8; i++) {
            bmn = fminf(bmn, smn[i]);
            bmx = fmaxf(bmx, smx[i]);
        }
        atomicMin(&g_mm[v * 2], fenc(bmn));
        atomicMax(&g_mm[v * 2 + 1], fenc(bmx));
    }
}

// ------------------------- kernel 5: normalize -------------------------
__global__ void __launch_bounds__(256) k_norm(float* __restrict__ out) {
    const int v = blockIdx.y;
    const int id = blockIdx.x * 256 + threadIdx.x;
    const int b = id / (IMG * IMG);
    const int rem = id - b * (IMG * IMG);
    float mn = fdec(g_mm[v * 2]);
    float mx = fdec(g_mm[v * 2 + 1]);
    float span = mx - mn;
    size_t o = ((size_t)b * 3 + v) * (IMG * IMG) + rem;
    float val = out[o];
    out[o] = (span < 1e-8f) ? 0.f : (val - mn) / (span + 1e-8f);
}

// ----------------------------- launch -----------------------------
extern "C" void kernel_launch(void* const* d_in, const int* in_sizes, int n_in,
                              void* d_out, int out_size) {
    const float* x = (const float*)d_in[0];
    float* out = (float*)d_out;

    k_init<<<1, 32>>>();
    k_rowstats<<<Bn * En, 256>>>(x);
    k_colmean<<<dim3(Nn / 256, Bn), 256>>>(x);
    k_gemm<<<dim3(10, Bn), 256>>>();
    const int pix_blocks = (Bn * IMG * IMG) / 256;  // 6272, exact
    k_resize<<<dim3(pix_blocks, 3), 256>>>(out);
    k_norm<<<dim3(pix_blocks, 3), 256>>>(out);
}

// round 4
// speedup vs baseline: 1.3940x; 1.3940x over previous
#include <cuda_runtime.h>
#include <cuda_bf16.h>
#include <mma.h>
#include <cstdint>

using namespace nvcuda;

#define Bn 32
#define En 512
#define Nn 4096
#define IMG 224

#define KC 64                    // K elements per chunk
#define NCHUNK (Nn / KC)         // 64
#define STAGES 3
#define LDT 72                   // padded smem leading dim (elements)
#define TILE_BYTES (128 * LDT * 2)          // 18432 per operand tile
#define STAGE_BYTES (2 * TILE_BYTES)        // 36864 (A + B)
#define GEMM_SMEM (STAGES * STAGE_BYTES)    // 110592

// ----------------------------- device scratch -----------------------------
__device__ __nv_bfloat16 g_xbf[(size_t)Bn * En * Nn];   // 134 MB bf16 copy of x
__device__ float g_mean[Bn * En];                        // row means
__device__ float g_inv[Bn * En];                         // 1/(||x-mean||+1e-8)
__device__ float g_spatial[Bn * Nn];                     // column means
__device__ float g_corr[(size_t)Bn * En * En];           // raw Gram G = x x^T
__device__ unsigned g_mm[6];                             // encoded min/max per view

// ----------------------------- helpers -----------------------------
__device__ __forceinline__ unsigned fenc(float f) {
    unsigned u = __float_as_uint(f);
    return (u & 0x80000000u) ? ~u : (u | 0x80000000u);
}
__device__ __forceinline__ float fdec(unsigned e) {
    return (e & 0x80000000u) ? __uint_as_float(e ^ 0x80000000u)
                             : __uint_as_float(~e);
}
__device__ __forceinline__ uint32_t s2u(const void* p) {
    uint32_t a;
    asm("{ .reg .u64 t; cvta.to.shared.u64 t, %1; cvt.u32.u64 %0, t; }"
        : "=r"(a) : "l"(p));
    return a;
}
__device__ __forceinline__ void cp16(uint32_t dst, const void* src) {
    asm volatile("cp.async.cg.shared.global [%0], [%1], 16;" :: "r"(dst), "l"(src));
}
__device__ __forceinline__ void cp_commit() {
    asm volatile("cp.async.commit_group;" ::: "memory");
}
__device__ __forceinline__ void cp_wait2() {
    asm volatile("cp.async.wait_group 2;" ::: "memory");
}
__device__ __forceinline__ void cp_wait0() {
    asm volatile("cp.async.wait_group 0;" ::: "memory");
}

// ----------------------------- kernel 0: init -----------------------------
__global__ void k_init() {
    int t = threadIdx.x;
    if (t < 6) g_mm[t] = (t & 1) ? 0u : 0xFFFFFFFFu;
}

// ------------------- kernel 1: row stats + bf16 convert -------------------
__global__ void __launch_bounds__(256) k_rowstats(const float* __restrict__ x) {
    const int row = blockIdx.x;
    const float4* src = reinterpret_cast<const float4*>(x) + (size_t)row * (Nn / 4);
    uint2* dst = reinterpret_cast<uint2*>(g_xbf) + (size_t)row * (Nn / 4);
    float s = 0.f, ss = 0.f;
#pragma unroll
    for (int k = 0; k < 4; k++) {
        int i = threadIdx.x + k * 256;
        float4 v = src[i];
        s += v.x + v.y + v.z + v.w;
        ss += v.x * v.x + v.y * v.y + v.z * v.z + v.w * v.w;
        unsigned ax = (unsigned)__bfloat16_as_ushort(__float2bfloat16_rn(v.x));
        unsigned ay = (unsigned)__bfloat16_as_ushort(__float2bfloat16_rn(v.y));
        unsigned az = (unsigned)__bfloat16_as_ushort(__float2bfloat16_rn(v.z));
        unsigned aw = (unsigned)__bfloat16_as_ushort(__float2bfloat16_rn(v.w));
        uint2 o;
        o.x = ax | (ay << 16);
        o.y = az | (aw << 16);
        dst[i] = o;
    }
#pragma unroll
    for (int o = 16; o; o >>= 1) {
        s += __shfl_down_sync(0xFFFFFFFFu, s, o);
        ss += __shfl_down_sync(0xFFFFFFFFu, ss, o);
    }
    __shared__ float sh[16];
    int w = threadIdx.x >> 5, l = threadIdx.x & 31;
    if (l == 0) { sh[w] = s; sh[w + 8] = ss; }
    __syncthreads();
    if (threadIdx.x == 0) {
        float S = 0.f, SS = 0.f;
#pragma unroll
        for (int i = 0; i < 8; i++) { S += sh[i]; SS += sh[i + 8]; }
        float m = S * (1.f / (float)Nn);
        g_mean[row] = m;
        float var = SS - S * m;
        float r = sqrtf(fmaxf(var, 0.f));
        g_inv[row] = 1.f / (r + 1e-8f);
    }
}

// ------------------ kernel 2: column means (from bf16 copy) ------------------
// 128 blocks x 256 threads; each thread sums 4 columns over 512 rows.
__global__ void __launch_bounds__(256) k_colmean() {
    int T = blockIdx.x * 256 + threadIdx.x;   // 0..32767
    int b = T >> 10;                           // batch
    int g = T & 1023;                          // 4-column group
    const uint2* p = reinterpret_cast<const uint2*>(g_xbf + (size_t)b * En * Nn) + g;
    float s0 = 0.f, s1 = 0.f, s2 = 0.f, s3 = 0.f;
#pragma unroll 8
    for (int e = 0; e < En; e++) {
        uint2 v = p[(size_t)e * (Nn / 4)];
        s0 += __uint_as_float(v.x << 16);
        s1 += __uint_as_float(v.x & 0xFFFF0000u);
        s2 += __uint_as_float(v.y << 16);
        s3 += __uint_as_float(v.y & 0xFFFF0000u);
    }
    float4 o;
    o.x = s0 * (1.f / (float)En);
    o.y = s1 * (1.f / (float)En);
    o.z = s2 * (1.f / (float)En);
    o.w = s3 * (1.f / (float)En);
    reinterpret_cast<float4*>(g_spatial + b * Nn + g * 4)[0] = o;
}

// --------------- kernel 3: batched Gram (wmma + cp.async pipeline) ---------------
// 128x128 tiles, symmetric pairs (ti<=tj), KC=64, 3-stage cp.async pipeline.
__global__ void __launch_bounds__(256, 2) k_gemm() {
    extern __shared__ __align__(16) char dyn[];
    const uint32_t dynb = s2u(dyn);

    const int ti_tab[10] = {0, 0, 0, 0, 1, 1, 1, 2, 2, 3};
    const int tj_tab[10] = {0, 1, 2, 3, 1, 2, 3, 2, 3, 3};
    const int ti = ti_tab[blockIdx.x];
    const int tj = tj_tab[blockIdx.x];
    const bool diag = (ti == tj);
    const int b = blockIdx.y;
    const int t = threadIdx.x;
    const int wid = t >> 5;
    const int wm = wid >> 2;   // 0..1 : 64-row strip
    const int wn = wid & 3;    // 0..3 : 32-col strip

    const __nv_bfloat16* X = g_xbf + (size_t)b * En * Nn;
    const char* Arows = (const char*)(X + (size_t)ti * 128 * Nn);
    const char* Brows = (const char*)(X + (size_t)tj * 128 * Nn);

    // thread -> 4 load slots per tile: row r, 16B segment seg
    const int r_ld = t >> 1;                 // two threads per row? No: see below
    // Use idx = t + 256*q mapping: r = idx>>3 (0..127), seg = idx&7 (0..7)

    wmma::fragment<wmma::accumulator, 16, 16, 16, float> acc[4][2];
#pragma unroll
    for (int i = 0; i < 4; i++)
#pragma unroll
        for (int j = 0; j < 2; j++) wmma::fill_fragment(acc[i][j], 0.f);

    // ---- prefetch chunks 0..2 ----
#pragma unroll
    for (int j = 0; j < STAGES; j++) {
        uint32_t sb = dynb + j * STAGE_BYTES;
#pragma unroll
        for (int q = 0; q < 4; q++) {
            int idx = t + 256 * q;
            int r = idx >> 3, seg = idx & 7;
            uint32_t off = (uint32_t)(r * (LDT * 2) + seg * 16);
            cp16(sb + off, Arows + (size_t)r * 8192 + (size_t)j * 128 + seg * 16);
            if (!diag)
                cp16(sb + TILE_BYTES + off,
                     Brows + (size_t)r * 8192 + (size_t)j * 128 + seg * 16);
        }
        cp_commit();
    }

    for (int i = 0; i < NCHUNK; i++) {
        cp_wait2();          // chunk i resident (<=2 groups pending)
        __syncthreads();

        const int st = i % STAGES;
        const __nv_bfloat16* sA =
            reinterpret_cast<const __nv_bfloat16*>(dyn + st * STAGE_BYTES);
        const __nv_bfloat16* sB = diag ? sA : (sA + 128 * LDT);

#pragma unroll
        for (int kk = 0; kk < 4; kk++) {
            wmma::fragment<wmma::matrix_a, 16, 16, 16, __nv_bfloat16,
                           wmma::row_major> af[4];
            wmma::fragment<wmma::matrix_b, 16, 16, 16, __nv_bfloat16,
                           wmma::col_major> bf[2];
#pragma unroll
            for (int x = 0; x < 4; x++)
                wmma::load_matrix_sync(af[x], &sA[(wm * 64 + x * 16) * LDT + kk * 16],
                                       LDT);
#pragma unroll
            for (int y = 0; y < 2; y++)
                wmma::load_matrix_sync(bf[y], &sB[(wn * 32 + y * 16) * LDT + kk * 16],
                                       LDT);
#pragma unroll
            for (int x = 0; x < 4; x++)
#pragma unroll
                for (int y = 0; y < 2; y++)
                    wmma::mma_sync(acc[x][y], af[x], bf[y], acc[x][y]);
        }
        __syncthreads();     // all warps done with stage st before refill

        const int jn = i + STAGES;
        if (jn < NCHUNK) {
            uint32_t sb = dynb + st * STAGE_BYTES;
#pragma unroll
            for (int q = 0; q < 4; q++) {
                int idx = t + 256 * q;
                int r = idx >> 3, seg = idx & 7;
                uint32_t off = (uint32_t)(r * (LDT * 2) + seg * 16);
                cp16(sb + off, Arows + (size_t)r * 8192 + (size_t)jn * 128 + seg * 16);
                if (!diag)
                    cp16(sb + TILE_BYTES + off,
                         Brows + (size_t)r * 8192 + (size_t)jn * 128 + seg * 16);
            }
        }
        cp_commit();          // commit even when empty to keep group accounting fixed
    }
    cp_wait0();

    // ---- epilogue: direct + mirrored stores ----
    float* C = g_corr + (size_t)b * En * En;
#pragma unroll
    for (int x = 0; x < 4; x++) {
#pragma unroll
        for (int y = 0; y < 2; y++) {
            int rm = ti * 128 + wm * 64 + x * 16;
            int cn = tj * 128 + wn * 32 + y * 16;
            wmma::store_matrix_sync(&C[(size_t)rm * En + cn], acc[x][y], En,
                                    wmma::mem_row_major);
            if (!diag)
                wmma::store_matrix_sync(&C[(size_t)cn * En + rm], acc[x][y], En,
                                        wmma::mem_col_major);
        }
    }
}

// ---------------- kernel 4: bilinear resize + global min/max ----------------
__global__ void __launch_bounds__(256) k_resize(float* __restrict__ out) {
    const int v = blockIdx.y;
    const int id = blockIdx.x * 256 + threadIdx.x;
    const int b = id / (IMG * IMG);
    const int rem = id - b * (IMG * IMG);
    const int y = rem / IMG;
    const int xw = rem - y * IMG;

    const int size = (v == 0) ? 23 : (v == 1) ? 64 : 512;
    const float scale = (float)size / (float)IMG;

    float rr = fmaxf(((float)y + 0.5f) * scale - 0.5f, 0.f);
    int r0 = min((int)floorf(rr), size - 1);
    int r1 = min(r0 + 1, size - 1);
    float wr = rr - (float)r0;
    float cc = fmaxf(((float)xw + 0.5f) * scale - 0.5f, 0.f);
    int c0 = min((int)floorf(cc), size - 1);
    int c1 = min(c0 + 1, size - 1);
    float wc = cc - (float)c0;

    float v00, v01, v10, v11;
    if (v == 0) {
        const float* M = g_mean + b * En;
        int g00 = r0 * 23 + c0, g01 = r0 * 23 + c1, g10 = r1 * 23 + c0, g11 = r1 * 23 + c1;
        v00 = (g00 < En) ? M[g00] : 0.f;
        v01 = (g01 < En) ? M[g01] : 0.f;
        v10 = (g10 < En) ? M[g10] : 0.f;
        v11 = (g11 < En) ? M[g11] : 0.f;
    } else if (v == 1) {
        const float* S = g_spatial + b * Nn;
        v00 = S[r0 * 64 + c0]; v01 = S[r0 * 64 + c1];
        v10 = S[r1 * 64 + c0]; v11 = S[r1 * 64 + c1];
    } else {
        const float* C = g_corr + (size_t)b * En * En;
        const float* M = g_mean + b * En;
        const float* I = g_inv + b * En;
        float m0 = M[r0], m1 = M[r1], i0 = I[r0], i1 = I[r1];
        float mc0 = M[c0], mc1 = M[c1], ic0 = I[c0], ic1 = I[c1];
        v00 = (C[(size_t)r0 * En + c0] - (float)Nn * m0 * mc0) * i0 * ic0;
        v01 = (C[(size_t)r0 * En + c1] - (float)Nn * m0 * mc1) * i0 * ic1;
        v10 = (C[(size_t)r1 * En + c0] - (float)Nn * m1 * mc0) * i1 * ic0;
        v11 = (C[(size_t)r1 * En + c1] - (float)Nn * m1 * mc1) * i1 * ic1;
    }
    float top = v00 * (1.f - wc) + v01 * wc;
    float bot = v10 * (1.f - wc) + v11 * wc;
    float val = top * (1.f - wr) + bot * wr;

    out[((size_t)b * 3 + v) * (IMG * IMG) + rem] = val;

    float mn = val, mx = val;
#pragma unroll
    for (int o = 16; o; o >>= 1) {
        mn = fminf(mn, __shfl_down_sync(0xFFFFFFFFu, mn, o));
        mx = fmaxf(mx, __shfl_down_sync(0xFFFFFFFFu, mx, o));
    }
    __shared__ float smn[8], smx[8];
    int w = threadIdx.x >> 5, l = threadIdx.x & 31;
    if (l == 0) { smn[w] = mn; smx[w] = mx; }
    __syncthreads();
    if (threadIdx.x == 0) {
        float bmn = smn[0], bmx = smx[0];
#pragma unroll
        for (int i = 1; i < 8; i++) {
            bmn = fminf(bmn, smn[i]);
            bmx = fmaxf(bmx, smx[i]);
        }
        atomicMin(&g_mm[v * 2], fenc(bmn));
        atomicMax(&g_mm[v * 2 + 1], fenc(bmx));
    }
}

// ------------------------- kernel 5: normalize -------------------------
__global__ void __launch_bounds__(256) k_norm(float* __restrict__ out) {
    const int v = blockIdx.y;
    const int id = blockIdx.x * 256 + threadIdx.x;
    const int b = id / (IMG * IMG);
    const int rem = id - b * (IMG * IMG);
    float mn = fdec(g_mm[v * 2]);
    float mx = fdec(g_mm[v * 2 + 1]);
    float span = mx - mn;
    size_t o = ((size_t)b * 3 + v) * (IMG * IMG) + rem;
    float val = out[o];
    out[o] = (span < 1e-8f) ? 0.f : (val - mn) / (span + 1e-8f);
}

// ----------------------------- launch -----------------------------
extern "C" void kernel_launch(void* const* d_in, const int* in_sizes, int n_in,
                              void* d_out, int out_size) {
    const float* x = (const float*)d_in[0];
    float* out = (float*)d_out;

    static int configured = 0;
    if (!configured) {
        cudaFuncSetAttribute(k_gemm, cudaFuncAttributeMaxDynamicSharedMemorySize,
                             GEMM_SMEM);
        configured = 1;
    }

    k_init<<<1, 32>>>();
    k_rowstats<<<Bn * En, 256>>>(x);
    k_colmean<<<128, 256>>>();
    k_gemm<<<dim3(10, Bn), 256, GEMM_SMEM>>>();
    const int pix_blocks = (Bn * IMG * IMG) / 256;  // 6272
    k_resize<<<dim3(pix_blocks, 3), 256>>>(out);
    k_norm<<<dim3(pix_blocks, 3), 256>>>(out);
}